// round 13
// baseline (speedup 1.0000x reference)
#include <cuda_runtime.h>
#include <cuda_fp16.h>
#include <cuda_bf16.h>
#include <math.h>

#define NN 50000
#define MAXE 1600000
#define H 128
#define CC 40
#define EPS 1e-5f

// ---------------- static device scratch ----------------
__device__ __half g_hw[NN * H];      // GEMM output pre-scaled by dis[row], fp16
__device__ float g_agg[NN * H];      // aggregation output (fp32)
__device__ float g_dis[NN];
__device__ int   g_cnt[NN];
__device__ int   g_rowptr[NN + 1];
__device__ int   g_cursor[NN];
__device__ int   g_csrc[MAXE];
__device__ int   g_bsum[128];
__device__ float g_stats[6 * 128];   // [layer][sum(128) | sumsq(128)] x3
__device__ __nv_bfloat16 g_wthi[2][H * H];   // ping-pong W^T hi
__device__ __nv_bfloat16 g_wtlo[2][H * H];   // ping-pong W^T lo
__device__ float g_logits_scratch[NN * CC];

// ---------------- CSR build ----------------
__global__ void k_zero_cnt(int* __restrict__ cnt, float* __restrict__ stats, int n) {
    int i = blockIdx.x * blockDim.x + threadIdx.x;
    if (i < n) cnt[i] = 0;
    if (i < 6 * 128) stats[i] = 0.0f;
}

__global__ void k_count(const int* __restrict__ dst, int* __restrict__ cnt, int e) {
    int i = blockIdx.x * blockDim.x + threadIdx.x;
    if (i < e) atomicAdd(&cnt[dst[i]], 1);
}

// scan pass 1 + dis computation fused
__global__ __launch_bounds__(1024)
void k_scan_blk(const int* __restrict__ cnt, int* __restrict__ rowptr,
                int* __restrict__ bsum, float* __restrict__ dis, int n) {
    __shared__ int warpsums[32];
    int tid = threadIdx.x;
    int lane = tid & 31, wid = tid >> 5;
    int i = blockIdx.x * 1024 + tid;
    int v = (i < n) ? cnt[i] : 0;
    if (i < n) dis[i] = rsqrtf((float)(v + 1));
    int x = v;
#pragma unroll
    for (int o = 1; o < 32; o <<= 1) {
        int t = __shfl_up_sync(0xffffffffu, x, o);
        if (lane >= o) x += t;
    }
    if (lane == 31) warpsums[wid] = x;
    __syncthreads();
    if (wid == 0) {
        int w = warpsums[lane];
#pragma unroll
        for (int o = 1; o < 32; o <<= 1) {
            int t = __shfl_up_sync(0xffffffffu, w, o);
            if (lane >= o) w += t;
        }
        warpsums[lane] = w;
    }
    __syncthreads();
    int excl = x - v + (wid > 0 ? warpsums[wid - 1] : 0);
    if (i < n) rowptr[i] = excl;
    if (tid == 1023) bsum[blockIdx.x] = excl + v;
}

// pass 2: add block-prefix, init cursor
__global__ __launch_bounds__(1024)
void k_scan_add(int* __restrict__ rowptr, int* __restrict__ cursor,
                const int* __restrict__ bsum, int n, int e) {
    __shared__ int s_off;
    if (threadIdx.x < 32) {
        int nb = (int)blockIdx.x;
        int lane = threadIdx.x;
        int s = 0;
        if (lane < nb) s += bsum[lane];
        if (lane + 32 < nb) s += bsum[lane + 32];
        if (lane + 64 < nb) s += bsum[lane + 64];
#pragma unroll
        for (int o = 16; o > 0; o >>= 1) s += __shfl_down_sync(0xffffffffu, s, o);
        if (lane == 0) s_off = s;
    }
    __syncthreads();
    int i = blockIdx.x * 1024 + threadIdx.x;
    if (i < n) {
        int v = rowptr[i] + s_off;
        rowptr[i] = v;
        cursor[i] = v;
    }
    if (i == 0) rowptr[n] = e;
}

__global__ void k_fill(const int* __restrict__ src, const int* __restrict__ dst,
                       int* __restrict__ cursor, int* __restrict__ csrc, int e) {
    int i = blockIdx.x * blockDim.x + threadIdx.x;
    if (i >= e) return;
    int s = src[i], d = dst[i];
    int pos = atomicAdd(&cursor[d], 1);
    csrc[pos] = s;
}

// ---------------- W split ----------------
__global__ void k_wsplit(const float* __restrict__ W, __nv_bfloat16* __restrict__ wth,
                         __nv_bfloat16* __restrict__ wtl) {
    int i = blockIdx.x * blockDim.x + threadIdx.x;
    if (i >= H * H) return;
    int k = i >> 7, nn = i & 127;
    float v = W[i];
    __nv_bfloat16 h = __float2bfloat16(v);
    float rem = v - __bfloat162float(h);
    wth[nn * H + k] = h;
    wtl[nn * H + k] = __float2bfloat16(rem);
}

// ---------------- GEMM via bf16 split MMA; in-kernel BN; epilogue scales by dis ----------------
__device__ __forceinline__ void mma16816(float* c, const unsigned* a, const unsigned* b) {
    asm volatile(
        "mma.sync.aligned.m16n8k16.row.col.f32.bf16.bf16.f32 "
        "{%0,%1,%2,%3}, {%4,%5,%6,%7}, {%8,%9}, {%0,%1,%2,%3};"
        : "+f"(c[0]), "+f"(c[1]), "+f"(c[2]), "+f"(c[3])
        : "r"(a[0]), "r"(a[1]), "r"(a[2]), "r"(a[3]), "r"(b[0]), "r"(b[1]));
}

#define APITCH 40

__global__ __launch_bounds__(256, 2)
void k_gemm_mma(const float* __restrict__ A,
                const unsigned* __restrict__ wth,
                const unsigned* __restrict__ wtl,
                const float* __restrict__ gamma, const float* __restrict__ beta,
                const float* __restrict__ stats,      // sum[128] | sumsq[128]; null => identity
                const float* __restrict__ dis,
                __half* __restrict__ Cout, int n) {
    __shared__ __nv_bfloat16 As_hi[128 * APITCH];
    __shared__ __nv_bfloat16 As_lo[128 * APITCH];
    __shared__ __nv_bfloat16 Ws_hi[128 * APITCH];
    __shared__ __nv_bfloat16 Ws_lo[128 * APITCH];
    __shared__ float sscale[128];
    __shared__ float sshift[128];

    int tid = threadIdx.x;
    if (tid < 128) {
        if (stats) {
            float inv_n = 1.0f / (float)n;
            float mean = stats[tid] * inv_n;
            float var = fmaxf(stats[128 + tid] * inv_n - mean * mean, 0.0f);
            float iv = rsqrtf(var + EPS);
            float sc = gamma[tid] * iv;
            sscale[tid] = sc;
            sshift[tid] = beta[tid] - mean * sc;
        } else {
            sscale[tid] = 1.0f;
            sshift[tid] = 0.0f;
        }
    }
    __syncthreads();

    int w = tid >> 5, lane = tid & 31;
    int wm = w >> 2, wn = w & 3;
    int g = lane >> 2, tig = lane & 3;
    int row0blk = blockIdx.x * 128;
    bool bn = (stats != nullptr);

    float acc[4][4][4];
#pragma unroll
    for (int a = 0; a < 4; a++)
#pragma unroll
        for (int b = 0; b < 4; b++)
#pragma unroll
            for (int c = 0; c < 4; c++) acc[a][b][c] = 0.0f;

    for (int k0 = 0; k0 < 128; k0 += 32) {
        for (int i = tid; i < 128 * 32; i += 256) {
            int r = i >> 5, c = i & 31;
            int gr = row0blk + r;
            float v = 0.0f;
            if (gr < n) {
                v = A[(size_t)gr * 128 + k0 + c];
                if (bn) v = fmaxf(v * sscale[k0 + c] + sshift[k0 + c], 0.0f);
            }
            __nv_bfloat16 h = __float2bfloat16(v);
            As_hi[r * APITCH + c] = h;
            As_lo[r * APITCH + c] = __float2bfloat16(v - __bfloat162float(h));
        }
        for (int i = tid; i < 2048; i += 256) {
            int nn = i >> 4, kk = i & 15;
            ((unsigned*)&Ws_hi[nn * APITCH])[kk] = wth[nn * 64 + (k0 >> 1) + kk];
            ((unsigned*)&Ws_lo[nn * APITCH])[kk] = wtl[nn * 64 + (k0 >> 1) + kk];
        }
        __syncthreads();

#pragma unroll
        for (int ks = 0; ks < 2; ks++) {
            int ca = ks * 16 + 2 * tig;
            unsigned ah[4][4], al[4][4];
#pragma unroll
            for (int mf = 0; mf < 4; mf++) {
                int r0 = (wm * 64 + mf * 16 + g) * APITCH;
                int r1 = r0 + 8 * APITCH;
                ah[mf][0] = *(const unsigned*)&As_hi[r0 + ca];
                ah[mf][1] = *(const unsigned*)&As_hi[r1 + ca];
                ah[mf][2] = *(const unsigned*)&As_hi[r0 + ca + 8];
                ah[mf][3] = *(const unsigned*)&As_hi[r1 + ca + 8];
                al[mf][0] = *(const unsigned*)&As_lo[r0 + ca];
                al[mf][1] = *(const unsigned*)&As_lo[r1 + ca];
                al[mf][2] = *(const unsigned*)&As_lo[r0 + ca + 8];
                al[mf][3] = *(const unsigned*)&As_lo[r1 + ca + 8];
            }
#pragma unroll
            for (int nf = 0; nf < 4; nf++) {
                int nb = (wn * 32 + nf * 8 + g) * APITCH;
                unsigned bh[2], bl[2];
                bh[0] = *(const unsigned*)&Ws_hi[nb + ca];
                bh[1] = *(const unsigned*)&Ws_hi[nb + ca + 8];
                bl[0] = *(const unsigned*)&Ws_lo[nb + ca];
                bl[1] = *(const unsigned*)&Ws_lo[nb + ca + 8];
#pragma unroll
                for (int mf = 0; mf < 4; mf++) {
                    mma16816(acc[mf][nf], ah[mf], bh);
                    mma16816(acc[mf][nf], ah[mf], bl);
                    mma16816(acc[mf][nf], al[mf], bh);
                }
            }
        }
        __syncthreads();
    }

#pragma unroll
    for (int mf = 0; mf < 4; mf++) {
        int gr0 = row0blk + wm * 64 + mf * 16 + g;
        int gr1 = gr0 + 8;
        float ds0 = (gr0 < n) ? dis[gr0] : 0.0f;
        float ds1 = (gr1 < n) ? dis[gr1] : 0.0f;
#pragma unroll
        for (int nf = 0; nf < 4; nf++) {
            int col = wn * 32 + nf * 8 + 2 * tig;
            if (gr0 < n) {
                __half2 h = __floats2half2_rn(acc[mf][nf][0] * ds0, acc[mf][nf][1] * ds0);
                *(unsigned*)&Cout[(size_t)gr0 * 128 + col] = *(unsigned*)&h;
            }
            if (gr1 < n) {
                __half2 h = __floats2half2_rn(acc[mf][nf][2] * ds1, acc[mf][nf][3] * ds1);
                *(unsigned*)&Cout[(size_t)gr1 * 128 + col] = *(unsigned*)&h;
            }
        }
    }
}

// ---------------- pull aggregation: 2 nodes per warp interleaved, pairwise add tree ----------------
__device__ __forceinline__ float4 row2f4(const uint2& a) {
    float2 p = __half22float2(*(__half2*)&a.x);
    float2 q = __half22float2(*(__half2*)&a.y);
    return make_float4(p.x, p.y, q.x, q.y);
}
__device__ __forceinline__ void add4(float4& a, const float4& b) {
    a.x += b.x; a.y += b.y; a.z += b.z; a.w += b.w;
}

__global__ __launch_bounds__(256)
void k_aggregate(const __half* __restrict__ hw, const int* __restrict__ rowptr,
                 const int* __restrict__ csrc,
                 const float* __restrict__ bias, const float* __restrict__ dis,
                 float* __restrict__ agg, float* __restrict__ stats, int n) {
    __shared__ float ssum[128];
    __shared__ float ssq[128];
    int tid = threadIdx.x;
    if (tid < 128) { ssum[tid] = 0.0f; ssq[tid] = 0.0f; }
    __syncthreads();

    int warp = tid >> 5, lane = tid & 31;
    int nodeA = blockIdx.x * 16 + warp * 2;
    int nodeB = nodeA + 1;
    const uint2* hw2 = (const uint2*)hw;
    float4 b4 = ((const float4*)bias)[lane];

    bool hasA = nodeA < n, hasB = nodeB < n;
    float4 accA = make_float4(0, 0, 0, 0), accB = make_float4(0, 0, 0, 0);
    int jA = 0, endA = 0, jB = 0, endB = 0;
    if (hasA) {
        accA = row2f4(__ldg(&hw2[(size_t)nodeA * 32 + lane]));
        jA = rowptr[nodeA]; endA = rowptr[nodeA + 1];
    }
    if (hasB) {
        accB = row2f4(__ldg(&hw2[(size_t)nodeB * 32 + lane]));
        jB = rowptr[nodeB]; endB = rowptr[nodeB + 1];
    }

    // interleaved main loop: 4 edges per node per iteration (8 gathers in flight)
    while (jA + 3 < endA && jB + 3 < endB) {
        int a0 = __ldg(&csrc[jA]);
        int a1 = __ldg(&csrc[jA + 1]);
        int a2 = __ldg(&csrc[jA + 2]);
        int a3 = __ldg(&csrc[jA + 3]);
        int b0 = __ldg(&csrc[jB]);
        int b1 = __ldg(&csrc[jB + 1]);
        int b2 = __ldg(&csrc[jB + 2]);
        int b3 = __ldg(&csrc[jB + 3]);
        uint2 ra0 = __ldg(&hw2[(size_t)a0 * 32 + lane]);
        uint2 ra1 = __ldg(&hw2[(size_t)a1 * 32 + lane]);
        uint2 ra2 = __ldg(&hw2[(size_t)a2 * 32 + lane]);
        uint2 ra3 = __ldg(&hw2[(size_t)a3 * 32 + lane]);
        uint2 rb0 = __ldg(&hw2[(size_t)b0 * 32 + lane]);
        uint2 rb1 = __ldg(&hw2[(size_t)b1 * 32 + lane]);
        uint2 rb2 = __ldg(&hw2[(size_t)b2 * 32 + lane]);
        uint2 rb3 = __ldg(&hw2[(size_t)b3 * 32 + lane]);
        // pairwise tree per node
        float4 sA0 = row2f4(ra0), sA1 = row2f4(ra1), sA2 = row2f4(ra2), sA3 = row2f4(ra3);
        float4 sB0 = row2f4(rb0), sB1 = row2f4(rb1), sB2 = row2f4(rb2), sB3 = row2f4(rb3);
        add4(sA0, sA1); add4(sA2, sA3); add4(sA0, sA2); add4(accA, sA0);
        add4(sB0, sB1); add4(sB2, sB3); add4(sB0, sB2); add4(accB, sB0);
        jA += 4; jB += 4;
    }
    // drain A
    for (; jA + 3 < endA; jA += 4) {
        int a0 = __ldg(&csrc[jA]);
        int a1 = __ldg(&csrc[jA + 1]);
        int a2 = __ldg(&csrc[jA + 2]);
        int a3 = __ldg(&csrc[jA + 3]);
        float4 s0 = row2f4(__ldg(&hw2[(size_t)a0 * 32 + lane]));
        float4 s1 = row2f4(__ldg(&hw2[(size_t)a1 * 32 + lane]));
        float4 s2 = row2f4(__ldg(&hw2[(size_t)a2 * 32 + lane]));
        float4 s3 = row2f4(__ldg(&hw2[(size_t)a3 * 32 + lane]));
        add4(s0, s1); add4(s2, s3); add4(s0, s2); add4(accA, s0);
    }
    for (; jA < endA; jA++) {
        int a0 = __ldg(&csrc[jA]);
        add4(accA, row2f4(__ldg(&hw2[(size_t)a0 * 32 + lane])));
    }
    // drain B
    for (; jB + 3 < endB; jB += 4) {
        int b0 = __ldg(&csrc[jB]);
        int b1 = __ldg(&csrc[jB + 1]);
        int b2 = __ldg(&csrc[jB + 2]);
        int b3 = __ldg(&csrc[jB + 3]);
        float4 s0 = row2f4(__ldg(&hw2[(size_t)b0 * 32 + lane]));
        float4 s1 = row2f4(__ldg(&hw2[(size_t)b1 * 32 + lane]));
        float4 s2 = row2f4(__ldg(&hw2[(size_t)b2 * 32 + lane]));
        float4 s3 = row2f4(__ldg(&hw2[(size_t)b3 * 32 + lane]));
        add4(s0, s1); add4(s2, s3); add4(s0, s2); add4(accB, s0);
    }
    for (; jB < endB; jB++) {
        int b0 = __ldg(&csrc[jB]);
        add4(accB, row2f4(__ldg(&hw2[(size_t)b0 * 32 + lane])));
    }

    int c = lane * 4;
    if (hasA) {
        float dd = dis[nodeA];
        float4 outv;
        outv.x = b4.x + dd * accA.x;
        outv.y = b4.y + dd * accA.y;
        outv.z = b4.z + dd * accA.z;
        outv.w = b4.w + dd * accA.w;
        ((float4*)agg)[(size_t)nodeA * 32 + lane] = outv;
        atomicAdd(&ssum[c + 0], outv.x); atomicAdd(&ssq[c + 0], outv.x * outv.x);
        atomicAdd(&ssum[c + 1], outv.y); atomicAdd(&ssq[c + 1], outv.y * outv.y);
        atomicAdd(&ssum[c + 2], outv.z); atomicAdd(&ssq[c + 2], outv.z * outv.z);
        atomicAdd(&ssum[c + 3], outv.w); atomicAdd(&ssq[c + 3], outv.w * outv.w);
    }
    if (hasB) {
        float dd = dis[nodeB];
        float4 outv;
        outv.x = b4.x + dd * accB.x;
        outv.y = b4.y + dd * accB.y;
        outv.z = b4.z + dd * accB.z;
        outv.w = b4.w + dd * accB.w;
        ((float4*)agg)[(size_t)nodeB * 32 + lane] = outv;
        atomicAdd(&ssum[c + 0], outv.x); atomicAdd(&ssq[c + 0], outv.x * outv.x);
        atomicAdd(&ssum[c + 1], outv.y); atomicAdd(&ssq[c + 1], outv.y * outv.y);
        atomicAdd(&ssum[c + 2], outv.z); atomicAdd(&ssq[c + 2], outv.z * outv.z);
        atomicAdd(&ssum[c + 3], outv.w); atomicAdd(&ssq[c + 3], outv.w * outv.w);
    }
    __syncthreads();
    if (tid < 128) {
        atomicAdd(&stats[tid], ssum[tid]);
        atomicAdd(&stats[128 + tid], ssq[tid]);
    }
}

// ---------------- head: in-kernel BN3 -> FC -> ReLU -> log_softmax ----------------
__global__ __launch_bounds__(256)
void k_head(const float* __restrict__ agg, const float* __restrict__ fcW,
            const float* __restrict__ fcb, const float* __restrict__ gamma,
            const float* __restrict__ beta, const float* __restrict__ stats,
            float* __restrict__ lsm, float* __restrict__ logits, int n) {
    __shared__ float Wf[128 * 40];
    __shared__ float fb[40];
    __shared__ float hs[32][129];
    __shared__ float lg[32][40];
    __shared__ float nlse[32];
    __shared__ float sscale[128];
    __shared__ float sshift[128];

    int tid = threadIdx.x;
    if (tid < 128) {
        float inv_n = 1.0f / (float)n;
        float mean = stats[tid] * inv_n;
        float var = fmaxf(stats[128 + tid] * inv_n - mean * mean, 0.0f);
        float iv = rsqrtf(var + EPS);
        float sc = gamma[tid] * iv;
        sscale[tid] = sc;
        sshift[tid] = beta[tid] - mean * sc;
    }
    for (int i = tid; i < 128 * 40; i += 256) Wf[i] = fcW[i];
    if (tid < 40) fb[tid] = fcb[tid];
    __syncthreads();

    int node0 = blockIdx.x * 32;
    for (int i = tid; i < 32 * 128; i += 256) {
        int r = i >> 7, c = i & 127;
        int gn = node0 + r;
        float v = 0.0f;
        if (gn < n) {
            v = agg[(size_t)gn * 128 + c];
            v = fmaxf(v * sscale[c] + sshift[c], 0.0f);
        }
        hs[r][c] = v;
    }
    __syncthreads();

    int nd = tid >> 3;
    int cg = (tid & 7) * 5;
    float acc[5] = {0, 0, 0, 0, 0};
    for (int k = 0; k < 128; k++) {
        float h = hs[nd][k];
#pragma unroll
        for (int j = 0; j < 5; j++) acc[j] += h * Wf[k * 40 + cg + j];
    }
#pragma unroll
    for (int j = 0; j < 5; j++) lg[nd][cg + j] = fmaxf(acc[j] + fb[cg + j], 0.0f);
    __syncthreads();

    if (tid < 32) {
        float m = -1e30f;
        for (int c = 0; c < 40; c++) m = fmaxf(m, lg[tid][c]);
        float s = 0.0f;
        for (int c = 0; c < 40; c++) s += expf(lg[tid][c] - m);
        nlse[tid] = m + logf(s);
    }
    __syncthreads();

    for (int i = tid; i < 32 * 40; i += 256) {
        int r = i / 40, c = i - r * 40;
        int gn = node0 + r;
        if (gn < n) {
            float l = lg[r][c];
            logits[(size_t)gn * 40 + c] = l;
            lsm[(size_t)gn * 40 + c] = l - nlse[r];
        }
    }
}

// ---------------- host ----------------
extern "C" void kernel_launch(void* const* d_in, const int* in_sizes, int n_in,
                              void* d_out, int out_size) {
    const float* x   = (const float*)d_in[0];
    const int*   ei  = (const int*)d_in[1];
    const float* W1  = (const float*)d_in[2];
    const float* b1  = (const float*)d_in[3];
    const float* W2  = (const float*)d_in[4];
    const float* b2  = (const float*)d_in[5];
    const float* W3  = (const float*)d_in[6];
    const float* b3  = (const float*)d_in[7];
    const float* g1  = (const float*)d_in[8];
    const float* be1 = (const float*)d_in[9];
    const float* g2  = (const float*)d_in[10];
    const float* be2 = (const float*)d_in[11];
    const float* g3  = (const float*)d_in[12];
    const float* be3 = (const float*)d_in[13];
    const float* fcW = (const float*)d_in[14];
    const float* fcb = (const float*)d_in[15];

    int n = in_sizes[0] / H;
    int e = in_sizes[1] / 2;
    const int* src = ei;
    const int* dst = ei + e;

    float *agg, *dis, *stats, *lscr;
    __half* hw;
    __nv_bfloat16 *wth0, *wtl0, *wth1, *wtl1;
    int *cnt, *rowptr, *cursor, *csrc, *bsum;
    cudaGetSymbolAddress((void**)&hw, g_hw);
    cudaGetSymbolAddress((void**)&agg, g_agg);
    cudaGetSymbolAddress((void**)&dis, g_dis);
    cudaGetSymbolAddress((void**)&cnt, g_cnt);
    cudaGetSymbolAddress((void**)&rowptr, g_rowptr);
    cudaGetSymbolAddress((void**)&cursor, g_cursor);
    cudaGetSymbolAddress((void**)&csrc, g_csrc);
    cudaGetSymbolAddress((void**)&bsum, g_bsum);
    cudaGetSymbolAddress((void**)&stats, g_stats);
    cudaGetSymbolAddress((void**)&wth0, g_wthi);
    cudaGetSymbolAddress((void**)&wtl0, g_wtlo);
    wth1 = wth0 + H * H;
    wtl1 = wtl0 + H * H;
    cudaGetSymbolAddress((void**)&lscr, g_logits_scratch);

    float* lsm = (float*)d_out;
    float* logits = (out_size >= 2 * n * CC) ? (lsm + (size_t)n * CC) : lscr;

    // persistent aux stream + events (host-side only; created once)
    static cudaStream_t saux = nullptr;
    static cudaEvent_t ev0 = nullptr, evdis = nullptr, evg1 = nullptr,
                       evw2 = nullptr, evw3 = nullptr;
    if (!saux) {
        cudaStreamCreateWithFlags(&saux, cudaStreamNonBlocking);
        cudaEventCreateWithFlags(&ev0, cudaEventDisableTiming);
        cudaEventCreateWithFlags(&evdis, cudaEventDisableTiming);
        cudaEventCreateWithFlags(&evg1, cudaEventDisableTiming);
        cudaEventCreateWithFlags(&evw2, cudaEventDisableTiming);
        cudaEventCreateWithFlags(&evw3, cudaEventDisableTiming);
    }
    cudaStream_t s0 = 0;

    int nb = (n + 255) / 256;
    int ebks = (e + 255) / 256;
    int gemm_blocks = (n + 127) / 128;
    int agg_blocks = (n + 15) / 16;
    int scan_blocks = (n + 1023) / 1024;
    int ws_blocks = (H * H + 255) / 256;

    float* st0 = stats;
    float* st1 = stats + 256;
    float* st2 = stats + 512;

    // fork aux stream into capture
    cudaEventRecord(ev0, s0);
    cudaStreamWaitEvent(saux, ev0, 0);

    // ---- s0: CSR build ----
    k_zero_cnt<<<nb, 256, 0, s0>>>(cnt, stats, n);
    k_count<<<ebks, 256, 0, s0>>>(dst, cnt, e);
    k_scan_blk<<<scan_blocks, 1024, 0, s0>>>(cnt, rowptr, bsum, dis, n);
    cudaEventRecord(evdis, s0);
    k_scan_add<<<scan_blocks, 1024, 0, s0>>>(rowptr, cursor, bsum, n, e);
    k_fill<<<ebks, 256, 0, s0>>>(src, dst, cursor, csrc, e);

    // ---- saux: wsplit1 || CSR; gemm1 after dis; wsplit2/3 after gemm1 ----
    k_wsplit<<<ws_blocks, 256, 0, saux>>>(W1, wth0, wtl0);
    cudaStreamWaitEvent(saux, evdis, 0);
    k_gemm_mma<<<gemm_blocks, 256, 0, saux>>>(x, (const unsigned*)wth0, (const unsigned*)wtl0,
                                              nullptr, nullptr, nullptr, dis, hw, n);
    cudaEventRecord(evg1, saux);
    k_wsplit<<<ws_blocks, 256, 0, saux>>>(W2, wth1, wtl1);
    cudaEventRecord(evw2, saux);
    k_wsplit<<<ws_blocks, 256, 0, saux>>>(W3, wth0, wtl0);
    cudaEventRecord(evw3, saux);

    // ---- s0: layer 1 aggregate ----
    cudaStreamWaitEvent(s0, evg1, 0);
    k_aggregate<<<agg_blocks, 256, 0, s0>>>(hw, rowptr, csrc, b1, dis, agg, st0, n);

    // ---- layer 2 ----
    cudaStreamWaitEvent(s0, evw2, 0);
    k_gemm_mma<<<gemm_blocks, 256, 0, s0>>>(agg, (const unsigned*)wth1, (const unsigned*)wtl1,
                                            g1, be1, st0, dis, hw, n);
    k_aggregate<<<agg_blocks, 256, 0, s0>>>(hw, rowptr, csrc, b2, dis, agg, st1, n);

    // ---- layer 3 ----
    cudaStreamWaitEvent(s0, evw3, 0);
    k_gemm_mma<<<gemm_blocks, 256, 0, s0>>>(agg, (const unsigned*)wth0, (const unsigned*)wtl0,
                                            g2, be2, st1, dis, hw, n);
    k_aggregate<<<agg_blocks, 256, 0, s0>>>(hw, rowptr, csrc, b3, dis, agg, st2, n);

    // ---- head ----
    k_head<<<(n + 31) / 32, 256, 0, s0>>>(agg, fcW, fcb, g3, be3, st2, lsm, logits, n);
}

// round 16
// speedup vs baseline: 1.1513x; 1.1513x over previous
#include <cuda_runtime.h>
#include <cuda_fp16.h>
#include <cuda_bf16.h>
#include <math.h>

#define NN 50000
#define MAXE 1600000
#define H 128
#define CC 40
#define EPS 1e-5f

// ---------------- static device scratch ----------------
__device__ __half g_hw[NN * H];      // GEMM output pre-scaled by dis[row], fp16
__device__ float g_agg[NN * H];      // aggregation output (fp32)
__device__ float g_dis[NN];
__device__ int   g_cnt[NN];
__device__ int   g_rowptr[NN + 1];
__device__ int   g_cursor[NN];
__device__ int   g_csrc[MAXE];
__device__ int   g_bsum[128];
__device__ float g_stats[6 * 128];   // [layer][sum(128) | sumsq(128)] x3
__device__ __nv_bfloat16 g_wthi[2][H * H];   // ping-pong W^T hi
__device__ __nv_bfloat16 g_wtlo[2][H * H];   // ping-pong W^T lo
__device__ __nv_bfloat16 g_fwth[CC * H];     // fcW^T hi  [n][k]
__device__ __nv_bfloat16 g_fwtl[CC * H];     // fcW^T lo
__device__ float g_logits_scratch[NN * CC];

// ---------------- CSR build ----------------
__global__ void k_zero_cnt(int* __restrict__ cnt, float* __restrict__ stats, int n) {
    int i = blockIdx.x * blockDim.x + threadIdx.x;
    if (i < n) cnt[i] = 0;
    if (i < 6 * 128) stats[i] = 0.0f;
}

__global__ void k_count(const int* __restrict__ dst, int* __restrict__ cnt, int e) {
    int i = blockIdx.x * blockDim.x + threadIdx.x;
    if (i < e) atomicAdd(&cnt[dst[i]], 1);
}

__global__ __launch_bounds__(1024)
void k_scan_blk(const int* __restrict__ cnt, int* __restrict__ rowptr,
                int* __restrict__ bsum, float* __restrict__ dis, int n) {
    __shared__ int warpsums[32];
    int tid = threadIdx.x;
    int lane = tid & 31, wid = tid >> 5;
    int i = blockIdx.x * 1024 + tid;
    int v = (i < n) ? cnt[i] : 0;
    if (i < n) dis[i] = rsqrtf((float)(v + 1));
    int x = v;
#pragma unroll
    for (int o = 1; o < 32; o <<= 1) {
        int t = __shfl_up_sync(0xffffffffu, x, o);
        if (lane >= o) x += t;
    }
    if (lane == 31) warpsums[wid] = x;
    __syncthreads();
    if (wid == 0) {
        int w = warpsums[lane];
#pragma unroll
        for (int o = 1; o < 32; o <<= 1) {
            int t = __shfl_up_sync(0xffffffffu, w, o);
            if (lane >= o) w += t;
        }
        warpsums[lane] = w;
    }
    __syncthreads();
    int excl = x - v + (wid > 0 ? warpsums[wid - 1] : 0);
    if (i < n) rowptr[i] = excl;
    if (tid == 1023) bsum[blockIdx.x] = excl + v;
}

__global__ __launch_bounds__(1024)
void k_scan_add(int* __restrict__ rowptr, int* __restrict__ cursor,
                const int* __restrict__ bsum, int n, int e) {
    __shared__ int s_off;
    if (threadIdx.x < 32) {
        int nb = (int)blockIdx.x;
        int lane = threadIdx.x;
        int s = 0;
        if (lane < nb) s += bsum[lane];
        if (lane + 32 < nb) s += bsum[lane + 32];
        if (lane + 64 < nb) s += bsum[lane + 64];
#pragma unroll
        for (int o = 16; o > 0; o >>= 1) s += __shfl_down_sync(0xffffffffu, s, o);
        if (lane == 0) s_off = s;
    }
    __syncthreads();
    int i = blockIdx.x * 1024 + threadIdx.x;
    if (i < n) {
        int v = rowptr[i] + s_off;
        rowptr[i] = v;
        cursor[i] = v;
    }
    if (i == 0) rowptr[n] = e;
}

__global__ void k_fill(const int* __restrict__ src, const int* __restrict__ dst,
                       int* __restrict__ cursor, int* __restrict__ csrc, int e) {
    int i = blockIdx.x * blockDim.x + threadIdx.x;
    if (i >= e) return;
    int s = src[i], d = dst[i];
    int pos = atomicAdd(&cursor[d], 1);
    csrc[pos] = s;
}

// ---------------- W splits ----------------
__global__ void k_wsplit(const float* __restrict__ W, __nv_bfloat16* __restrict__ wth,
                         __nv_bfloat16* __restrict__ wtl) {
    int i = blockIdx.x * blockDim.x + threadIdx.x;
    if (i >= H * H) return;
    int k = i >> 7, nn = i & 127;
    float v = W[i];
    __nv_bfloat16 h = __float2bfloat16(v);
    float rem = v - __bfloat162float(h);
    wth[nn * H + k] = h;
    wtl[nn * H + k] = __float2bfloat16(rem);
}

__global__ void k_wsplit_head(const float* __restrict__ W, __nv_bfloat16* __restrict__ wth,
                              __nv_bfloat16* __restrict__ wtl) {
    int i = blockIdx.x * blockDim.x + threadIdx.x;   // over 128*40
    if (i >= H * CC) return;
    int k = i / CC, nn = i - k * CC;
    float v = W[i];
    __nv_bfloat16 h = __float2bfloat16(v);
    float rem = v - __bfloat162float(h);
    wth[nn * H + k] = h;
    wtl[nn * H + k] = __float2bfloat16(rem);
}

// ---------------- GEMM via bf16 split MMA; in-kernel BN; epilogue scales by dis ----------------
__device__ __forceinline__ void mma16816(float* c, const unsigned* a, const unsigned* b) {
    asm volatile(
        "mma.sync.aligned.m16n8k16.row.col.f32.bf16.bf16.f32 "
        "{%0,%1,%2,%3}, {%4,%5,%6,%7}, {%8,%9}, {%0,%1,%2,%3};"
        : "+f"(c[0]), "+f"(c[1]), "+f"(c[2]), "+f"(c[3])
        : "r"(a[0]), "r"(a[1]), "r"(a[2]), "r"(a[3]), "r"(b[0]), "r"(b[1]));
}

#define APITCH 40

__global__ __launch_bounds__(256, 2)
void k_gemm_mma(const float* __restrict__ A,
                const unsigned* __restrict__ wth,
                const unsigned* __restrict__ wtl,
                const float* __restrict__ gamma, const float* __restrict__ beta,
                const float* __restrict__ stats,      // sum[128] | sumsq[128]; null => identity
                const float* __restrict__ dis,
                __half* __restrict__ Cout, int n) {
    __shared__ __nv_bfloat16 As_hi[128 * APITCH];
    __shared__ __nv_bfloat16 As_lo[128 * APITCH];
    __shared__ __nv_bfloat16 Ws_hi[128 * APITCH];
    __shared__ __nv_bfloat16 Ws_lo[128 * APITCH];
    __shared__ float sscale[128];
    __shared__ float sshift[128];

    int tid = threadIdx.x;
    if (tid < 128) {
        if (stats) {
            float inv_n = 1.0f / (float)n;
            float mean = stats[tid] * inv_n;
            float var = fmaxf(stats[128 + tid] * inv_n - mean * mean, 0.0f);
            float iv = rsqrtf(var + EPS);
            float sc = gamma[tid] * iv;
            sscale[tid] = sc;
            sshift[tid] = beta[tid] - mean * sc;
        } else {
            sscale[tid] = 1.0f;
            sshift[tid] = 0.0f;
        }
    }
    __syncthreads();

    int w = tid >> 5, lane = tid & 31;
    int wm = w >> 2, wn = w & 3;
    int g = lane >> 2, tig = lane & 3;
    int row0blk = blockIdx.x * 128;
    bool bn = (stats != nullptr);

    float acc[4][4][4];
#pragma unroll
    for (int a = 0; a < 4; a++)
#pragma unroll
        for (int b = 0; b < 4; b++)
#pragma unroll
            for (int c = 0; c < 4; c++) acc[a][b][c] = 0.0f;

    for (int k0 = 0; k0 < 128; k0 += 32) {
        for (int i = tid; i < 128 * 32; i += 256) {
            int r = i >> 5, c = i & 31;
            int gr = row0blk + r;
            float v = 0.0f;
            if (gr < n) {
                v = A[(size_t)gr * 128 + k0 + c];
                if (bn) v = fmaxf(v * sscale[k0 + c] + sshift[k0 + c], 0.0f);
            }
            __nv_bfloat16 h = __float2bfloat16(v);
            As_hi[r * APITCH + c] = h;
            As_lo[r * APITCH + c] = __float2bfloat16(v - __bfloat162float(h));
        }
        for (int i = tid; i < 2048; i += 256) {
            int nn = i >> 4, kk = i & 15;
            ((unsigned*)&Ws_hi[nn * APITCH])[kk] = wth[nn * 64 + (k0 >> 1) + kk];
            ((unsigned*)&Ws_lo[nn * APITCH])[kk] = wtl[nn * 64 + (k0 >> 1) + kk];
        }
        __syncthreads();

#pragma unroll
        for (int ks = 0; ks < 2; ks++) {
            int ca = ks * 16 + 2 * tig;
            unsigned ah[4][4], al[4][4];
#pragma unroll
            for (int mf = 0; mf < 4; mf++) {
                int r0 = (wm * 64 + mf * 16 + g) * APITCH;
                int r1 = r0 + 8 * APITCH;
                ah[mf][0] = *(const unsigned*)&As_hi[r0 + ca];
                ah[mf][1] = *(const unsigned*)&As_hi[r1 + ca];
                ah[mf][2] = *(const unsigned*)&As_hi[r0 + ca + 8];
                ah[mf][3] = *(const unsigned*)&As_hi[r1 + ca + 8];
                al[mf][0] = *(const unsigned*)&As_lo[r0 + ca];
                al[mf][1] = *(const unsigned*)&As_lo[r1 + ca];
                al[mf][2] = *(const unsigned*)&As_lo[r0 + ca + 8];
                al[mf][3] = *(const unsigned*)&As_lo[r1 + ca + 8];
            }
#pragma unroll
            for (int nf = 0; nf < 4; nf++) {
                int nb = (wn * 32 + nf * 8 + g) * APITCH;
                unsigned bh[2], bl[2];
                bh[0] = *(const unsigned*)&Ws_hi[nb + ca];
                bh[1] = *(const unsigned*)&Ws_hi[nb + ca + 8];
                bl[0] = *(const unsigned*)&Ws_lo[nb + ca];
                bl[1] = *(const unsigned*)&Ws_lo[nb + ca + 8];
#pragma unroll
                for (int mf = 0; mf < 4; mf++) {
                    mma16816(acc[mf][nf], ah[mf], bh);
                    mma16816(acc[mf][nf], ah[mf], bl);
                    mma16816(acc[mf][nf], al[mf], bh);
                }
            }
        }
        __syncthreads();
    }

#pragma unroll
    for (int mf = 0; mf < 4; mf++) {
        int gr0 = row0blk + wm * 64 + mf * 16 + g;
        int gr1 = gr0 + 8;
        float ds0 = (gr0 < n) ? dis[gr0] : 0.0f;
        float ds1 = (gr1 < n) ? dis[gr1] : 0.0f;
#pragma unroll
        for (int nf = 0; nf < 4; nf++) {
            int col = wn * 32 + nf * 8 + 2 * tig;
            if (gr0 < n) {
                __half2 h = __floats2half2_rn(acc[mf][nf][0] * ds0, acc[mf][nf][1] * ds0);
                *(unsigned*)&Cout[(size_t)gr0 * 128 + col] = *(unsigned*)&h;
            }
            if (gr1 < n) {
                __half2 h = __floats2half2_rn(acc[mf][nf][2] * ds1, acc[mf][nf][3] * ds1);
                *(unsigned*)&Cout[(size_t)gr1 * 128 + col] = *(unsigned*)&h;
            }
        }
    }
}

// ---------------- pull aggregation: warp per node, unroll-8, uint2 gathers (R12 best) ----------------
__device__ __forceinline__ void acc_row(float4& acc, const uint2& a) {
    float2 p = __half22float2(*(__half2*)&a.x);
    float2 q = __half22float2(*(__half2*)&a.y);
    acc.x += p.x; acc.y += p.y; acc.z += q.x; acc.w += q.y;
}

__global__ __launch_bounds__(256)
void k_aggregate(const __half* __restrict__ hw, const int* __restrict__ rowptr,
                 const int* __restrict__ csrc,
                 const float* __restrict__ bias, const float* __restrict__ dis,
                 float* __restrict__ agg, float* __restrict__ stats, int n) {
    __shared__ float ssum[128];
    __shared__ float ssq[128];
    int tid = threadIdx.x;
    if (tid < 128) { ssum[tid] = 0.0f; ssq[tid] = 0.0f; }
    __syncthreads();

    int warp = tid >> 5, lane = tid & 31;
    int node = blockIdx.x * 8 + warp;
    if (node < n) {
        const uint2* hw2 = (const uint2*)hw;
        float dd = dis[node];
        float4 b = ((const float4*)bias)[lane];

        uint2 u0 = __ldg(&hw2[(size_t)node * 32 + lane]);
        float2 f0 = __half22float2(*(__half2*)&u0.x);
        float2 f1 = __half22float2(*(__half2*)&u0.y);
        float4 acc = make_float4(f0.x, f0.y, f1.x, f1.y);

        int j = rowptr[node];
        int end = rowptr[node + 1];
        for (; j + 7 < end; j += 8) {
            int i0 = __ldg(&csrc[j]);
            int i1 = __ldg(&csrc[j + 1]);
            int i2 = __ldg(&csrc[j + 2]);
            int i3 = __ldg(&csrc[j + 3]);
            int i4 = __ldg(&csrc[j + 4]);
            int i5 = __ldg(&csrc[j + 5]);
            int i6 = __ldg(&csrc[j + 6]);
            int i7 = __ldg(&csrc[j + 7]);
            uint2 a0 = __ldg(&hw2[(size_t)i0 * 32 + lane]);
            uint2 a1 = __ldg(&hw2[(size_t)i1 * 32 + lane]);
            uint2 a2 = __ldg(&hw2[(size_t)i2 * 32 + lane]);
            uint2 a3 = __ldg(&hw2[(size_t)i3 * 32 + lane]);
            uint2 a4 = __ldg(&hw2[(size_t)i4 * 32 + lane]);
            uint2 a5 = __ldg(&hw2[(size_t)i5 * 32 + lane]);
            uint2 a6 = __ldg(&hw2[(size_t)i6 * 32 + lane]);
            uint2 a7 = __ldg(&hw2[(size_t)i7 * 32 + lane]);
            acc_row(acc, a0); acc_row(acc, a1); acc_row(acc, a2); acc_row(acc, a3);
            acc_row(acc, a4); acc_row(acc, a5); acc_row(acc, a6); acc_row(acc, a7);
        }
        for (; j < end; j++) {
            int i0 = __ldg(&csrc[j]);
            uint2 a0 = __ldg(&hw2[(size_t)i0 * 32 + lane]);
            acc_row(acc, a0);
        }

        float4 outv;
        outv.x = b.x + dd * acc.x;
        outv.y = b.y + dd * acc.y;
        outv.z = b.z + dd * acc.z;
        outv.w = b.w + dd * acc.w;
        ((float4*)agg)[(size_t)node * 32 + lane] = outv;

        int c = lane * 4;
        atomicAdd(&ssum[c + 0], outv.x); atomicAdd(&ssq[c + 0], outv.x * outv.x);
        atomicAdd(&ssum[c + 1], outv.y); atomicAdd(&ssq[c + 1], outv.y * outv.y);
        atomicAdd(&ssum[c + 2], outv.z); atomicAdd(&ssq[c + 2], outv.z * outv.z);
        atomicAdd(&ssum[c + 3], outv.w); atomicAdd(&ssq[c + 3], outv.w * outv.w);
    }
    __syncthreads();
    if (tid < 128) {
        atomicAdd(&stats[tid], ssum[tid]);
        atomicAdd(&stats[128 + tid], ssq[tid]);
    }
}

// ---------------- head: BN3 -> FC (split bf16 MMA) -> ReLU -> log_softmax ----------------
__global__ __launch_bounds__(256)
void k_head_mma(const float* __restrict__ agg,
                const unsigned* __restrict__ fwth, const unsigned* __restrict__ fwtl,
                const float* __restrict__ fcb, const float* __restrict__ gamma,
                const float* __restrict__ beta, const float* __restrict__ stats,
                float* __restrict__ lsm, float* __restrict__ logits, int n) {
    __shared__ __nv_bfloat16 As_hi[128 * APITCH];
    __shared__ __nv_bfloat16 As_lo[128 * APITCH];
    __shared__ __nv_bfloat16 Ws_hi[CC * APITCH];
    __shared__ __nv_bfloat16 Ws_lo[CC * APITCH];
    __shared__ float sscale[128];
    __shared__ float sshift[128];
    __shared__ float fb[CC];

    int tid = threadIdx.x;
    if (tid < 128) {
        float inv_n = 1.0f / (float)n;
        float mean = stats[tid] * inv_n;
        float var = fmaxf(stats[128 + tid] * inv_n - mean * mean, 0.0f);
        float iv = rsqrtf(var + EPS);
        float sc = gamma[tid] * iv;
        sscale[tid] = sc;
        sshift[tid] = beta[tid] - mean * sc;
    }
    if (tid < CC) fb[tid] = fcb[tid];
    __syncthreads();

    int w = tid >> 5, lane = tid & 31;
    int g = lane >> 2, tig = lane & 3;
    int row0blk = blockIdx.x * 128;

    float acc[5][4];
#pragma unroll
    for (int a = 0; a < 5; a++)
#pragma unroll
        for (int c = 0; c < 4; c++) acc[a][c] = 0.0f;

    for (int k0 = 0; k0 < 128; k0 += 32) {
        // A chunk with BN+ReLU, split
        for (int i = tid; i < 128 * 32; i += 256) {
            int r = i >> 5, c = i & 31;
            int gr = row0blk + r;
            float v = 0.0f;
            if (gr < n) {
                v = agg[(size_t)gr * 128 + k0 + c];
                v = fmaxf(v * sscale[k0 + c] + sshift[k0 + c], 0.0f);
            }
            __nv_bfloat16 h = __float2bfloat16(v);
            As_hi[r * APITCH + c] = h;
            As_lo[r * APITCH + c] = __float2bfloat16(v - __bfloat162float(h));
        }
        // W chunk: 40 rows x 16 u32
        for (int i = tid; i < CC * 16; i += 256) {
            int nn = i >> 4, kk = i & 15;
            ((unsigned*)&Ws_hi[nn * APITCH])[kk] = fwth[nn * 64 + (k0 >> 1) + kk];
            ((unsigned*)&Ws_lo[nn * APITCH])[kk] = fwtl[nn * 64 + (k0 >> 1) + kk];
        }
        __syncthreads();

#pragma unroll
        for (int ks = 0; ks < 2; ks++) {
            int ca = ks * 16 + 2 * tig;
            unsigned ah[4], al[4];
            int r0 = (w * 16 + g) * APITCH;
            int r1 = r0 + 8 * APITCH;
            ah[0] = *(const unsigned*)&As_hi[r0 + ca];
            ah[1] = *(const unsigned*)&As_hi[r1 + ca];
            ah[2] = *(const unsigned*)&As_hi[r0 + ca + 8];
            ah[3] = *(const unsigned*)&As_hi[r1 + ca + 8];
            al[0] = *(const unsigned*)&As_lo[r0 + ca];
            al[1] = *(const unsigned*)&As_lo[r1 + ca];
            al[2] = *(const unsigned*)&As_lo[r0 + ca + 8];
            al[3] = *(const unsigned*)&As_lo[r1 + ca + 8];
#pragma unroll
            for (int nf = 0; nf < 5; nf++) {
                int nb = (nf * 8 + g) * APITCH;
                unsigned bh[2], bl[2];
                bh[0] = *(const unsigned*)&Ws_hi[nb + ca];
                bh[1] = *(const unsigned*)&Ws_hi[nb + ca + 8];
                bl[0] = *(const unsigned*)&Ws_lo[nb + ca];
                bl[1] = *(const unsigned*)&Ws_lo[nb + ca + 8];
                mma16816(acc[nf], ah, bh);
                mma16816(acc[nf], ah, bl);
                mma16816(acc[nf], al, bh);
            }
        }
        __syncthreads();
    }

    // epilogue: bias + relu; per-row log-softmax via quad reduction
    int gr0 = row0blk + w * 16 + g;
    int gr1 = gr0 + 8;
    float v0[10], v1[10];   // row0 / row1, 5 frags x 2 cols each
#pragma unroll
    for (int nf = 0; nf < 5; nf++) {
        int col = nf * 8 + tig * 2;
        v0[nf * 2 + 0] = fmaxf(acc[nf][0] + fb[col], 0.0f);
        v0[nf * 2 + 1] = fmaxf(acc[nf][1] + fb[col + 1], 0.0f);
        v1[nf * 2 + 0] = fmaxf(acc[nf][2] + fb[col], 0.0f);
        v1[nf * 2 + 1] = fmaxf(acc[nf][3] + fb[col + 1], 0.0f);
    }
    // max over row (10 local + quad reduce across tig)
    float m0 = v0[0], m1 = v1[0];
#pragma unroll
    for (int i = 1; i < 10; i++) { m0 = fmaxf(m0, v0[i]); m1 = fmaxf(m1, v1[i]); }
    m0 = fmaxf(m0, __shfl_xor_sync(0xffffffffu, m0, 1));
    m0 = fmaxf(m0, __shfl_xor_sync(0xffffffffu, m0, 2));
    m1 = fmaxf(m1, __shfl_xor_sync(0xffffffffu, m1, 1));
    m1 = fmaxf(m1, __shfl_xor_sync(0xffffffffu, m1, 2));
    float s0 = 0.0f, s1 = 0.0f;
#pragma unroll
    for (int i = 0; i < 10; i++) { s0 += expf(v0[i] - m0); s1 += expf(v1[i] - m1); }
    s0 += __shfl_xor_sync(0xffffffffu, s0, 1);
    s0 += __shfl_xor_sync(0xffffffffu, s0, 2);
    s1 += __shfl_xor_sync(0xffffffffu, s1, 1);
    s1 += __shfl_xor_sync(0xffffffffu, s1, 2);
    float lse0 = m0 + logf(s0);
    float lse1 = m1 + logf(s1);

#pragma unroll
    for (int nf = 0; nf < 5; nf++) {
        int col = nf * 8 + tig * 2;
        if (gr0 < n) {
            logits[(size_t)gr0 * CC + col]     = v0[nf * 2 + 0];
            logits[(size_t)gr0 * CC + col + 1] = v0[nf * 2 + 1];
            lsm[(size_t)gr0 * CC + col]        = v0[nf * 2 + 0] - lse0;
            lsm[(size_t)gr0 * CC + col + 1]    = v0[nf * 2 + 1] - lse0;
        }
        if (gr1 < n) {
            logits[(size_t)gr1 * CC + col]     = v1[nf * 2 + 0];
            logits[(size_t)gr1 * CC + col + 1] = v1[nf * 2 + 1];
            lsm[(size_t)gr1 * CC + col]        = v1[nf * 2 + 0] - lse1;
            lsm[(size_t)gr1 * CC + col + 1]    = v1[nf * 2 + 1] - lse1;
        }
    }
}

// ---------------- host ----------------
extern "C" void kernel_launch(void* const* d_in, const int* in_sizes, int n_in,
                              void* d_out, int out_size) {
    const float* x   = (const float*)d_in[0];
    const int*   ei  = (const int*)d_in[1];
    const float* W1  = (const float*)d_in[2];
    const float* b1  = (const float*)d_in[3];
    const float* W2  = (const float*)d_in[4];
    const float* b2  = (const float*)d_in[5];
    const float* W3  = (const float*)d_in[6];
    const float* b3  = (const float*)d_in[7];
    const float* g1  = (const float*)d_in[8];
    const float* be1 = (const float*)d_in[9];
    const float* g2  = (const float*)d_in[10];
    const float* be2 = (const float*)d_in[11];
    const float* g3  = (const float*)d_in[12];
    const float* be3 = (const float*)d_in[13];
    const float* fcW = (const float*)d_in[14];
    const float* fcb = (const float*)d_in[15];

    int n = in_sizes[0] / H;
    int e = in_sizes[1] / 2;
    const int* src = ei;
    const int* dst = ei + e;

    float *agg, *dis, *stats, *lscr;
    __half* hw;
    __nv_bfloat16 *wth0, *wtl0, *wth1, *wtl1, *fwth, *fwtl;
    int *cnt, *rowptr, *cursor, *csrc, *bsum;
    cudaGetSymbolAddress((void**)&hw, g_hw);
    cudaGetSymbolAddress((void**)&agg, g_agg);
    cudaGetSymbolAddress((void**)&dis, g_dis);
    cudaGetSymbolAddress((void**)&cnt, g_cnt);
    cudaGetSymbolAddress((void**)&rowptr, g_rowptr);
    cudaGetSymbolAddress((void**)&cursor, g_cursor);
    cudaGetSymbolAddress((void**)&csrc, g_csrc);
    cudaGetSymbolAddress((void**)&bsum, g_bsum);
    cudaGetSymbolAddress((void**)&stats, g_stats);
    cudaGetSymbolAddress((void**)&wth0, g_wthi);
    cudaGetSymbolAddress((void**)&wtl0, g_wtlo);
    cudaGetSymbolAddress((void**)&fwth, g_fwth);
    cudaGetSymbolAddress((void**)&fwtl, g_fwtl);
    wth1 = wth0 + H * H;
    wtl1 = wtl0 + H * H;
    cudaGetSymbolAddress((void**)&lscr, g_logits_scratch);

    float* lsm = (float*)d_out;
    float* logits = (out_size >= 2 * n * CC) ? (lsm + (size_t)n * CC) : lscr;

    // persistent aux stream + events (host-side only; created once)
    static cudaStream_t saux = nullptr;
    static cudaEvent_t ev0 = nullptr, evdis = nullptr, evg1 = nullptr,
                       evw2 = nullptr, evw3 = nullptr, evwh = nullptr;
    if (!saux) {
        cudaStreamCreateWithFlags(&saux, cudaStreamNonBlocking);
        cudaEventCreateWithFlags(&ev0, cudaEventDisableTiming);
        cudaEventCreateWithFlags(&evdis, cudaEventDisableTiming);
        cudaEventCreateWithFlags(&evg1, cudaEventDisableTiming);
        cudaEventCreateWithFlags(&evw2, cudaEventDisableTiming);
        cudaEventCreateWithFlags(&evw3, cudaEventDisableTiming);
        cudaEventCreateWithFlags(&evwh, cudaEventDisableTiming);
    }
    cudaStream_t s0 = 0;

    int nb = (n + 255) / 256;
    int ebks = (e + 255) / 256;
    int gemm_blocks = (n + 127) / 128;
    int agg_blocks = (n + 7) / 8;
    int scan_blocks = (n + 1023) / 1024;
    int ws_blocks = (H * H + 255) / 256;
    int wsh_blocks = (H * CC + 255) / 256;

    float* st0 = stats;
    float* st1 = stats + 256;
    float* st2 = stats + 512;

    // fork aux stream into capture
    cudaEventRecord(ev0, s0);
    cudaStreamWaitEvent(saux, ev0, 0);

    // ---- s0: CSR build ----
    k_zero_cnt<<<nb, 256, 0, s0>>>(cnt, stats, n);
    k_count<<<ebks, 256, 0, s0>>>(dst, cnt, e);
    k_scan_blk<<<scan_blocks, 1024, 0, s0>>>(cnt, rowptr, bsum, dis, n);
    cudaEventRecord(evdis, s0);
    k_scan_add<<<scan_blocks, 1024, 0, s0>>>(rowptr, cursor, bsum, n, e);
    k_fill<<<ebks, 256, 0, s0>>>(src, dst, cursor, csrc, e);

    // ---- saux: wsplit1 || CSR; gemm1 after dis; wsplit2/3/head after gemm1 ----
    k_wsplit<<<ws_blocks, 256, 0, saux>>>(W1, wth0, wtl0);
    cudaStreamWaitEvent(saux, evdis, 0);
    k_gemm_mma<<<gemm_blocks, 256, 0, saux>>>(x, (const unsigned*)wth0, (const unsigned*)wtl0,
                                              nullptr, nullptr, nullptr, dis, hw, n);
    cudaEventRecord(evg1, saux);
    k_wsplit<<<ws_blocks, 256, 0, saux>>>(W2, wth1, wtl1);
    cudaEventRecord(evw2, saux);
    k_wsplit<<<ws_blocks, 256, 0, saux>>>(W3, wth0, wtl0);
    cudaEventRecord(evw3, saux);
    k_wsplit_head<<<wsh_blocks, 256, 0, saux>>>(fcW, fwth, fwtl);
    cudaEventRecord(evwh, saux);

    // ---- s0: layer 1 aggregate ----
    cudaStreamWaitEvent(s0, evg1, 0);
    k_aggregate<<<agg_blocks, 256, 0, s0>>>(hw, rowptr, csrc, b1, dis, agg, st0, n);

    // ---- layer 2 ----
    cudaStreamWaitEvent(s0, evw2, 0);
    k_gemm_mma<<<gemm_blocks, 256, 0, s0>>>(agg, (const unsigned*)wth1, (const unsigned*)wtl1,
                                            g1, be1, st0, dis, hw, n);
    k_aggregate<<<agg_blocks, 256, 0, s0>>>(hw, rowptr, csrc, b2, dis, agg, st1, n);

    // ---- layer 3 ----
    cudaStreamWaitEvent(s0, evw3, 0);
    k_gemm_mma<<<gemm_blocks, 256, 0, s0>>>(agg, (const unsigned*)wth0, (const unsigned*)wtl0,
                                            g2, be2, st1, dis, hw, n);
    k_aggregate<<<agg_blocks, 256, 0, s0>>>(hw, rowptr, csrc, b3, dis, agg, st2, n);

    // ---- head (MMA) ----
    cudaStreamWaitEvent(s0, evwh, 0);
    k_head_mma<<<gemm_blocks, 256, 0, s0>>>(agg, (const unsigned*)fwth, (const unsigned*)fwtl,
                                            fcb, g3, be3, st2, lsm, logits, n);
}

// round 17
// speedup vs baseline: 1.2078x; 1.0491x over previous
#include <cuda_runtime.h>
#include <cuda_fp16.h>
#include <cuda_bf16.h>
#include <math.h>

#define NN 50000
#define MAXE 1600000
#define H 128
#define CC 40
#define EPS 1e-5f

// ---------------- static device scratch ----------------
__device__ __half g_hw[NN * H];      // GEMM output (pre-scaled by dis[row] after k_scale_hw / epilogue), fp16
__device__ float g_agg[NN * H];      // aggregation output (fp32)
__device__ float g_dis[NN];
__device__ int   g_cnt[NN];
__device__ int   g_rowptr[NN + 1];
__device__ int   g_cursor[NN];
__device__ int   g_csrc[MAXE];
__device__ int   g_bsum[128];
__device__ float g_stats[6 * 128];   // [layer][sum(128) | sumsq(128)] x3
__device__ __nv_bfloat16 g_wthi[2][H * H];   // ping-pong W^T hi
__device__ __nv_bfloat16 g_wtlo[2][H * H];   // ping-pong W^T lo
__device__ __nv_bfloat16 g_fwth[CC * H];     // fcW^T hi  [n][k]
__device__ __nv_bfloat16 g_fwtl[CC * H];     // fcW^T lo
__device__ float g_logits_scratch[NN * CC];

// ---------------- CSR build ----------------
__global__ void k_zero_cnt(int* __restrict__ cnt, float* __restrict__ stats, int n) {
    int i = blockIdx.x * blockDim.x + threadIdx.x;
    if (i < n) cnt[i] = 0;
    if (i < 6 * 128) stats[i] = 0.0f;
}

__global__ void k_count(const int* __restrict__ dst, int* __restrict__ cnt, int e) {
    int i = blockIdx.x * blockDim.x + threadIdx.x;
    if (i < e) atomicAdd(&cnt[dst[i]], 1);
}

__global__ __launch_bounds__(1024)
void k_scan_blk(const int* __restrict__ cnt, int* __restrict__ rowptr,
                int* __restrict__ bsum, float* __restrict__ dis, int n) {
    __shared__ int warpsums[32];
    int tid = threadIdx.x;
    int lane = tid & 31, wid = tid >> 5;
    int i = blockIdx.x * 1024 + tid;
    int v = (i < n) ? cnt[i] : 0;
    if (i < n) dis[i] = rsqrtf((float)(v + 1));
    int x = v;
#pragma unroll
    for (int o = 1; o < 32; o <<= 1) {
        int t = __shfl_up_sync(0xffffffffu, x, o);
        if (lane >= o) x += t;
    }
    if (lane == 31) warpsums[wid] = x;
    __syncthreads();
    if (wid == 0) {
        int w = warpsums[lane];
#pragma unroll
        for (int o = 1; o < 32; o <<= 1) {
            int t = __shfl_up_sync(0xffffffffu, w, o);
            if (lane >= o) w += t;
        }
        warpsums[lane] = w;
    }
    __syncthreads();
    int excl = x - v + (wid > 0 ? warpsums[wid - 1] : 0);
    if (i < n) rowptr[i] = excl;
    if (tid == 1023) bsum[blockIdx.x] = excl + v;
}

__global__ __launch_bounds__(1024)
void k_scan_add(int* __restrict__ rowptr, int* __restrict__ cursor,
                const int* __restrict__ bsum, int n, int e) {
    __shared__ int s_off;
    if (threadIdx.x < 32) {
        int nb = (int)blockIdx.x;
        int lane = threadIdx.x;
        int s = 0;
        if (lane < nb) s += bsum[lane];
        if (lane + 32 < nb) s += bsum[lane + 32];
        if (lane + 64 < nb) s += bsum[lane + 64];
#pragma unroll
        for (int o = 16; o > 0; o >>= 1) s += __shfl_down_sync(0xffffffffu, s, o);
        if (lane == 0) s_off = s;
    }
    __syncthreads();
    int i = blockIdx.x * 1024 + threadIdx.x;
    if (i < n) {
        int v = rowptr[i] + s_off;
        rowptr[i] = v;
        cursor[i] = v;
    }
    if (i == 0) rowptr[n] = e;
}

__global__ void k_fill(const int* __restrict__ src, const int* __restrict__ dst,
                       int* __restrict__ cursor, int* __restrict__ csrc, int e) {
    int i = blockIdx.x * blockDim.x + threadIdx.x;
    if (i >= e) return;
    int s = src[i], d = dst[i];
    int pos = atomicAdd(&cursor[d], 1);
    csrc[pos] = s;
}

// ---------------- W splits ----------------
__global__ void k_wsplit(const float* __restrict__ W, __nv_bfloat16* __restrict__ wth,
                         __nv_bfloat16* __restrict__ wtl) {
    int i = blockIdx.x * blockDim.x + threadIdx.x;
    if (i >= H * H) return;
    int k = i >> 7, nn = i & 127;
    float v = W[i];
    __nv_bfloat16 h = __float2bfloat16(v);
    float rem = v - __bfloat162float(h);
    wth[nn * H + k] = h;
    wtl[nn * H + k] = __float2bfloat16(rem);
}

__global__ void k_wsplit_head(const float* __restrict__ W, __nv_bfloat16* __restrict__ wth,
                              __nv_bfloat16* __restrict__ wtl) {
    int i = blockIdx.x * blockDim.x + threadIdx.x;   // over 128*40
    if (i >= H * CC) return;
    int k = i / CC, nn = i - k * CC;
    float v = W[i];
    __nv_bfloat16 h = __float2bfloat16(v);
    float rem = v - __bfloat162float(h);
    wth[nn * H + k] = h;
    wtl[nn * H + k] = __float2bfloat16(rem);
}

// ---------------- post-scale hw rows by dis[row] (layer-1 decoupling) ----------------
__global__ void k_scale_hw(__half* __restrict__ hw, const float* __restrict__ dis, int n) {
    int i = blockIdx.x * blockDim.x + threadIdx.x;   // over n*32 uint2
    if (i >= n * 32) return;
    int node = i >> 5;
    float d = dis[node];
    uint2 v = ((uint2*)hw)[i];
    float2 p = __half22float2(*(__half2*)&v.x);
    float2 q = __half22float2(*(__half2*)&v.y);
    __half2 h0 = __floats2half2_rn(p.x * d, p.y * d);
    __half2 h1 = __floats2half2_rn(q.x * d, q.y * d);
    uint2 o;
    o.x = *(unsigned*)&h0;
    o.y = *(unsigned*)&h1;
    ((uint2*)hw)[i] = o;
}

// ---------------- GEMM via bf16 split MMA; in-kernel BN; reg double-buffered ----------------
__device__ __forceinline__ void mma16816(float* c, const unsigned* a, const unsigned* b) {
    asm volatile(
        "mma.sync.aligned.m16n8k16.row.col.f32.bf16.bf16.f32 "
        "{%0,%1,%2,%3}, {%4,%5,%6,%7}, {%8,%9}, {%0,%1,%2,%3};"
        : "+f"(c[0]), "+f"(c[1]), "+f"(c[2]), "+f"(c[3])
        : "r"(a[0]), "r"(a[1]), "r"(a[2]), "r"(a[3]), "r"(b[0]), "r"(b[1]));
}

#define APITCH 40

__global__ __launch_bounds__(256, 2)
void k_gemm_mma(const float* __restrict__ A,
                const unsigned* __restrict__ wth,
                const unsigned* __restrict__ wtl,
                const float* __restrict__ gamma, const float* __restrict__ beta,
                const float* __restrict__ stats,      // null => identity pre-op
                const float* __restrict__ dis,        // null => no epilogue scale
                __half* __restrict__ Cout, int n) {
    __shared__ __nv_bfloat16 As_hi[128 * APITCH];
    __shared__ __nv_bfloat16 As_lo[128 * APITCH];
    __shared__ __nv_bfloat16 Ws_hi[128 * APITCH];
    __shared__ __nv_bfloat16 Ws_lo[128 * APITCH];
    __shared__ float sscale[128];
    __shared__ float sshift[128];

    int tid = threadIdx.x;
    if (tid < 128) {
        if (stats) {
            float inv_n = 1.0f / (float)n;
            float mean = stats[tid] * inv_n;
            float var = fmaxf(stats[128 + tid] * inv_n - mean * mean, 0.0f);
            float iv = rsqrtf(var + EPS);
            float sc = gamma[tid] * iv;
            sscale[tid] = sc;
            sshift[tid] = beta[tid] - mean * sc;
        } else {
            sscale[tid] = 1.0f;
            sshift[tid] = 0.0f;
        }
    }
    __syncthreads();

    int w = tid >> 5, lane = tid & 31;
    int wm = w >> 2, wn = w & 3;
    int g = lane >> 2, tig = lane & 3;
    int row0blk = blockIdx.x * 128;
    bool bn = (stats != nullptr);

    float acc[4][4][4];
#pragma unroll
    for (int a = 0; a < 4; a++)
#pragma unroll
        for (int b = 0; b < 4; b++)
#pragma unroll
            for (int c = 0; c < 4; c++) acc[a][b][c] = 0.0f;

    // prefetch registers for A (16 fp32) and W (8+8 u32)
    float apf[16];
    unsigned whpf[8], wlpf[8];

#define LOAD_CHUNK(K0)                                                         \
    {                                                                          \
        _Pragma("unroll")                                                      \
        for (int i = 0; i < 16; i++) {                                         \
            int idx = tid + i * 256;                                           \
            int r = idx >> 5, c = idx & 31;                                    \
            int gr = row0blk + r;                                              \
            apf[i] = (gr < n) ? A[(size_t)gr * 128 + (K0) + c] : 0.0f;         \
        }                                                                      \
        _Pragma("unroll")                                                      \
        for (int i = 0; i < 8; i++) {                                          \
            int idx = tid + i * 256;                                           \
            int nn = idx >> 4, kk = idx & 15;                                  \
            whpf[i] = wth[nn * 64 + ((K0) >> 1) + kk];                         \
            wlpf[i] = wtl[nn * 64 + ((K0) >> 1) + kk];                         \
        }                                                                      \
    }

    LOAD_CHUNK(0);

    for (int k0 = 0; k0 < 128; k0 += 32) {
        // store prefetched chunk to smem (with BN+ReLU + hi/lo split)
#pragma unroll
        for (int i = 0; i < 16; i++) {
            int idx = tid + i * 256;
            int r = idx >> 5, c = idx & 31;
            float v = apf[i];
            if (bn) v = fmaxf(v * sscale[k0 + c] + sshift[k0 + c], 0.0f);
            __nv_bfloat16 h = __float2bfloat16(v);
            As_hi[r * APITCH + c] = h;
            As_lo[r * APITCH + c] = __float2bfloat16(v - __bfloat162float(h));
        }
#pragma unroll
        for (int i = 0; i < 8; i++) {
            int idx = tid + i * 256;
            int nn = idx >> 4, kk = idx & 15;
            ((unsigned*)&Ws_hi[nn * APITCH])[kk] = whpf[i];
            ((unsigned*)&Ws_lo[nn * APITCH])[kk] = wlpf[i];
        }
        __syncthreads();

        // issue next chunk's global loads to hide under the MMAs
        if (k0 < 96) LOAD_CHUNK(k0 + 32);

#pragma unroll
        for (int ks = 0; ks < 2; ks++) {
            int ca = ks * 16 + 2 * tig;
            unsigned ah[4][4], al[4][4];
#pragma unroll
            for (int mf = 0; mf < 4; mf++) {
                int r0 = (wm * 64 + mf * 16 + g) * APITCH;
                int r1 = r0 + 8 * APITCH;
                ah[mf][0] = *(const unsigned*)&As_hi[r0 + ca];
                ah[mf][1] = *(const unsigned*)&As_hi[r1 + ca];
                ah[mf][2] = *(const unsigned*)&As_hi[r0 + ca + 8];
                ah[mf][3] = *(const unsigned*)&As_hi[r1 + ca + 8];
                al[mf][0] = *(const unsigned*)&As_lo[r0 + ca];
                al[mf][1] = *(const unsigned*)&As_lo[r1 + ca];
                al[mf][2] = *(const unsigned*)&As_lo[r0 + ca + 8];
                al[mf][3] = *(const unsigned*)&As_lo[r1 + ca + 8];
            }
#pragma unroll
            for (int nf = 0; nf < 4; nf++) {
                int nb = (wn * 32 + nf * 8 + g) * APITCH;
                unsigned bh[2], bl[2];
                bh[0] = *(const unsigned*)&Ws_hi[nb + ca];
                bh[1] = *(const unsigned*)&Ws_hi[nb + ca + 8];
                bl[0] = *(const unsigned*)&Ws_lo[nb + ca];
                bl[1] = *(const unsigned*)&Ws_lo[nb + ca + 8];
#pragma unroll
                for (int mf = 0; mf < 4; mf++) {
                    mma16816(acc[mf][nf], ah[mf], bh);
                    mma16816(acc[mf][nf], ah[mf], bl);
                    mma16816(acc[mf][nf], al[mf], bh);
                }
            }
        }
        __syncthreads();
    }

#pragma unroll
    for (int mf = 0; mf < 4; mf++) {
        int gr0 = row0blk + wm * 64 + mf * 16 + g;
        int gr1 = gr0 + 8;
        float ds0 = dis ? ((gr0 < n) ? dis[gr0] : 0.0f) : 1.0f;
        float ds1 = dis ? ((gr1 < n) ? dis[gr1] : 0.0f) : 1.0f;
#pragma unroll
        for (int nf = 0; nf < 4; nf++) {
            int col = wn * 32 + nf * 8 + 2 * tig;
            if (gr0 < n) {
                __half2 h = __floats2half2_rn(acc[mf][nf][0] * ds0, acc[mf][nf][1] * ds0);
                *(unsigned*)&Cout[(size_t)gr0 * 128 + col] = *(unsigned*)&h;
            }
            if (gr1 < n) {
                __half2 h = __floats2half2_rn(acc[mf][nf][2] * ds1, acc[mf][nf][3] * ds1);
                *(unsigned*)&Cout[(size_t)gr1 * 128 + col] = *(unsigned*)&h;
            }
        }
    }
}

// ---------------- pull aggregation: warp per node, unroll-8, uint2 gathers ----------------
__device__ __forceinline__ void acc_row(float4& acc, const uint2& a) {
    float2 p = __half22float2(*(__half2*)&a.x);
    float2 q = __half22float2(*(__half2*)&a.y);
    acc.x += p.x; acc.y += p.y; acc.z += q.x; acc.w += q.y;
}

__global__ __launch_bounds__(256)
void k_aggregate(const __half* __restrict__ hw, const int* __restrict__ rowptr,
                 const int* __restrict__ csrc,
                 const float* __restrict__ bias, const float* __restrict__ dis,
                 float* __restrict__ agg, float* __restrict__ stats, int n) {
    __shared__ float ssum[128];
    __shared__ float ssq[128];
    int tid = threadIdx.x;
    if (tid < 128) { ssum[tid] = 0.0f; ssq[tid] = 0.0f; }
    __syncthreads();

    int warp = tid >> 5, lane = tid & 31;
    int node = blockIdx.x * 8 + warp;
    if (node < n) {
        const uint2* hw2 = (const uint2*)hw;
        float dd = dis[node];
        float4 b = ((const float4*)bias)[lane];

        uint2 u0 = __ldg(&hw2[(size_t)node * 32 + lane]);
        float2 f0 = __half22float2(*(__half2*)&u0.x);
        float2 f1 = __half22float2(*(__half2*)&u0.y);
        float4 acc = make_float4(f0.x, f0.y, f1.x, f1.y);

        int j = rowptr[node];
        int end = rowptr[node + 1];
        for (; j + 7 < end; j += 8) {
            int i0 = __ldg(&csrc[j]);
            int i1 = __ldg(&csrc[j + 1]);
            int i2 = __ldg(&csrc[j + 2]);
            int i3 = __ldg(&csrc[j + 3]);
            int i4 = __ldg(&csrc[j + 4]);
            int i5 = __ldg(&csrc[j + 5]);
            int i6 = __ldg(&csrc[j + 6]);
            int i7 = __ldg(&csrc[j + 7]);
            uint2 a0 = __ldg(&hw2[(size_t)i0 * 32 + lane]);
            uint2 a1 = __ldg(&hw2[(size_t)i1 * 32 + lane]);
            uint2 a2 = __ldg(&hw2[(size_t)i2 * 32 + lane]);
            uint2 a3 = __ldg(&hw2[(size_t)i3 * 32 + lane]);
            uint2 a4 = __ldg(&hw2[(size_t)i4 * 32 + lane]);
            uint2 a5 = __ldg(&hw2[(size_t)i5 * 32 + lane]);
            uint2 a6 = __ldg(&hw2[(size_t)i6 * 32 + lane]);
            uint2 a7 = __ldg(&hw2[(size_t)i7 * 32 + lane]);
            acc_row(acc, a0); acc_row(acc, a1); acc_row(acc, a2); acc_row(acc, a3);
            acc_row(acc, a4); acc_row(acc, a5); acc_row(acc, a6); acc_row(acc, a7);
        }
        for (; j < end; j++) {
            int i0 = __ldg(&csrc[j]);
            uint2 a0 = __ldg(&hw2[(size_t)i0 * 32 + lane]);
            acc_row(acc, a0);
        }

        float4 outv;
        outv.x = b.x + dd * acc.x;
        outv.y = b.y + dd * acc.y;
        outv.z = b.z + dd * acc.z;
        outv.w = b.w + dd * acc.w;
        ((float4*)agg)[(size_t)node * 32 + lane] = outv;

        int c = lane * 4;
        atomicAdd(&ssum[c + 0], outv.x); atomicAdd(&ssq[c + 0], outv.x * outv.x);
        atomicAdd(&ssum[c + 1], outv.y); atomicAdd(&ssq[c + 1], outv.y * outv.y);
        atomicAdd(&ssum[c + 2], outv.z); atomicAdd(&ssq[c + 2], outv.z * outv.z);
        atomicAdd(&ssum[c + 3], outv.w); atomicAdd(&ssq[c + 3], outv.w * outv.w);
    }
    __syncthreads();
    if (tid < 128) {
        atomicAdd(&stats[tid], ssum[tid]);
        atomicAdd(&stats[128 + tid], ssq[tid]);
    }
}

// ---------------- head: BN3 -> FC (split bf16 MMA) -> ReLU -> log_softmax ----------------
__global__ __launch_bounds__(256)
void k_head_mma(const float* __restrict__ agg,
                const unsigned* __restrict__ fwth, const unsigned* __restrict__ fwtl,
                const float* __restrict__ fcb, const float* __restrict__ gamma,
                const float* __restrict__ beta, const float* __restrict__ stats,
                float* __restrict__ lsm, float* __restrict__ logits, int n) {
    __shared__ __nv_bfloat16 As_hi[128 * APITCH];
    __shared__ __nv_bfloat16 As_lo[128 * APITCH];
    __shared__ __nv_bfloat16 Ws_hi[CC * APITCH];
    __shared__ __nv_bfloat16 Ws_lo[CC * APITCH];
    __shared__ float sscale[128];
    __shared__ float sshift[128];
    __shared__ float fb[CC];

    int tid = threadIdx.x;
    if (tid < 128) {
        float inv_n = 1.0f / (float)n;
        float mean = stats[tid] * inv_n;
        float var = fmaxf(stats[128 + tid] * inv_n - mean * mean, 0.0f);
        float iv = rsqrtf(var + EPS);
        float sc = gamma[tid] * iv;
        sscale[tid] = sc;
        sshift[tid] = beta[tid] - mean * sc;
    }
    if (tid < CC) fb[tid] = fcb[tid];
    __syncthreads();

    int w = tid >> 5, lane = tid & 31;
    int g = lane >> 2, tig = lane & 3;
    int row0blk = blockIdx.x * 128;

    float acc[5][4];
#pragma unroll
    for (int a = 0; a < 5; a++)
#pragma unroll
        for (int c = 0; c < 4; c++) acc[a][c] = 0.0f;

    float apf[16];
    unsigned whpf2[3], wlpf2[3];   // 40*16/256 = 2.5 -> 3 iters guarded

#define LOAD_CHUNK_H(K0)                                                       \
    {                                                                          \
        _Pragma("unroll")                                                      \
        for (int i = 0; i < 16; i++) {                                         \
            int idx = tid + i * 256;                                           \
            int r = idx >> 5, c = idx & 31;                                    \
            int gr = row0blk + r;                                              \
            apf[i] = (gr < n) ? agg[(size_t)gr * 128 + (K0) + c] : 0.0f;       \
        }                                                                      \
        _Pragma("unroll")                                                      \
        for (int i = 0; i < 3; i++) {                                          \
            int idx = tid + i * 256;                                           \
            if (idx < CC * 16) {                                               \
                int nn = idx >> 4, kk = idx & 15;                              \
                whpf2[i] = fwth[nn * 64 + ((K0) >> 1) + kk];                   \
                wlpf2[i] = fwtl[nn * 64 + ((K0) >> 1) + kk];                   \
            }                                                                  \
        }                                                                      \
    }

    LOAD_CHUNK_H(0);

    for (int k0 = 0; k0 < 128; k0 += 32) {
#pragma unroll
        for (int i = 0; i < 16; i++) {
            int idx = tid + i * 256;
            int r = idx >> 5, c = idx & 31;
            float v = fmaxf(apf[i] * sscale[k0 + c] + sshift[k0 + c], 0.0f);
            __nv_bfloat16 h = __float2bfloat16(v);
            As_hi[r * APITCH + c] = h;
            As_lo[r * APITCH + c] = __float2bfloat16(v - __bfloat162float(h));
        }
#pragma unroll
        for (int i = 0; i < 3; i++) {
            int idx = tid + i * 256;
            if (idx < CC * 16) {
                int nn = idx >> 4, kk = idx & 15;
                ((unsigned*)&Ws_hi[nn * APITCH])[kk] = whpf2[i];
                ((unsigned*)&Ws_lo[nn * APITCH])[kk] = wlpf2[i];
            }
        }
        __syncthreads();

        if (k0 < 96) LOAD_CHUNK_H(k0 + 32);

#pragma unroll
        for (int ks = 0; ks < 2; ks++) {
            int ca = ks * 16 + 2 * tig;
            unsigned ah[4], al[4];
            int r0 = (w * 16 + g) * APITCH;
            int r1 = r0 + 8 * APITCH;
            ah[0] = *(const unsigned*)&As_hi[r0 + ca];
            ah[1] = *(const unsigned*)&As_hi[r1 + ca];
            ah[2] = *(const unsigned*)&As_hi[r0 + ca + 8];
            ah[3] = *(const unsigned*)&As_hi[r1 + ca + 8];
            al[0] = *(const unsigned*)&As_lo[r0 + ca];
            al[1] = *(const unsigned*)&As_lo[r1 + ca];
            al[2] = *(const unsigned*)&As_lo[r0 + ca + 8];
            al[3] = *(const unsigned*)&As_lo[r1 + ca + 8];
#pragma unroll
            for (int nf = 0; nf < 5; nf++) {
                int nb = (nf * 8 + g) * APITCH;
                unsigned bh[2], bl[2];
                bh[0] = *(const unsigned*)&Ws_hi[nb + ca];
                bh[1] = *(const unsigned*)&Ws_hi[nb + ca + 8];
                bl[0] = *(const unsigned*)&Ws_lo[nb + ca];
                bl[1] = *(const unsigned*)&Ws_lo[nb + ca + 8];
                mma16816(acc[nf], ah, bh);
                mma16816(acc[nf], ah, bl);
                mma16816(acc[nf], al, bh);
            }
        }
        __syncthreads();
    }

    int gr0 = row0blk + w * 16 + g;
    int gr1 = gr0 + 8;
    float v0[10], v1[10];
#pragma unroll
    for (int nf = 0; nf < 5; nf++) {
        int col = nf * 8 + tig * 2;
        v0[nf * 2 + 0] = fmaxf(acc[nf][0] + fb[col], 0.0f);
        v0[nf * 2 + 1] = fmaxf(acc[nf][1] + fb[col + 1], 0.0f);
        v1[nf * 2 + 0] = fmaxf(acc[nf][2] + fb[col], 0.0f);
        v1[nf * 2 + 1] = fmaxf(acc[nf][3] + fb[col + 1], 0.0f);
    }
    float m0 = v0[0], m1 = v1[0];
#pragma unroll
    for (int i = 1; i < 10; i++) { m0 = fmaxf(m0, v0[i]); m1 = fmaxf(m1, v1[i]); }
    m0 = fmaxf(m0, __shfl_xor_sync(0xffffffffu, m0, 1));
    m0 = fmaxf(m0, __shfl_xor_sync(0xffffffffu, m0, 2));
    m1 = fmaxf(m1, __shfl_xor_sync(0xffffffffu, m1, 1));
    m1 = fmaxf(m1, __shfl_xor_sync(0xffffffffu, m1, 2));
    float s0 = 0.0f, s1 = 0.0f;
#pragma unroll
    for (int i = 0; i < 10; i++) { s0 += expf(v0[i] - m0); s1 += expf(v1[i] - m1); }
    s0 += __shfl_xor_sync(0xffffffffu, s0, 1);
    s0 += __shfl_xor_sync(0xffffffffu, s0, 2);
    s1 += __shfl_xor_sync(0xffffffffu, s1, 1);
    s1 += __shfl_xor_sync(0xffffffffu, s1, 2);
    float lse0 = m0 + logf(s0);
    float lse1 = m1 + logf(s1);

#pragma unroll
    for (int nf = 0; nf < 5; nf++) {
        int col = nf * 8 + tig * 2;
        if (gr0 < n) {
            logits[(size_t)gr0 * CC + col]     = v0[nf * 2 + 0];
            logits[(size_t)gr0 * CC + col + 1] = v0[nf * 2 + 1];
            lsm[(size_t)gr0 * CC + col]        = v0[nf * 2 + 0] - lse0;
            lsm[(size_t)gr0 * CC + col + 1]    = v0[nf * 2 + 1] - lse0;
        }
        if (gr1 < n) {
            logits[(size_t)gr1 * CC + col]     = v1[nf * 2 + 0];
            logits[(size_t)gr1 * CC + col + 1] = v1[nf * 2 + 1];
            lsm[(size_t)gr1 * CC + col]        = v1[nf * 2 + 0] - lse1;
            lsm[(size_t)gr1 * CC + col + 1]    = v1[nf * 2 + 1] - lse1;
        }
    }
}

// ---------------- host ----------------
extern "C" void kernel_launch(void* const* d_in, const int* in_sizes, int n_in,
                              void* d_out, int out_size) {
    const float* x   = (const float*)d_in[0];
    const int*   ei  = (const int*)d_in[1];
    const float* W1  = (const float*)d_in[2];
    const float* b1  = (const float*)d_in[3];
    const float* W2  = (const float*)d_in[4];
    const float* b2  = (const float*)d_in[5];
    const float* W3  = (const float*)d_in[6];
    const float* b3  = (const float*)d_in[7];
    const float* g1  = (const float*)d_in[8];
    const float* be1 = (const float*)d_in[9];
    const float* g2  = (const float*)d_in[10];
    const float* be2 = (const float*)d_in[11];
    const float* g3  = (const float*)d_in[12];
    const float* be3 = (const float*)d_in[13];
    const float* fcW = (const float*)d_in[14];
    const float* fcb = (const float*)d_in[15];

    int n = in_sizes[0] / H;
    int e = in_sizes[1] / 2;
    const int* src = ei;
    const int* dst = ei + e;

    float *agg, *dis, *stats, *lscr;
    __half* hw;
    __nv_bfloat16 *wth0, *wtl0, *wth1, *wtl1, *fwth, *fwtl;
    int *cnt, *rowptr, *cursor, *csrc, *bsum;
    cudaGetSymbolAddress((void**)&hw, g_hw);
    cudaGetSymbolAddress((void**)&agg, g_agg);
    cudaGetSymbolAddress((void**)&dis, g_dis);
    cudaGetSymbolAddress((void**)&cnt, g_cnt);
    cudaGetSymbolAddress((void**)&rowptr, g_rowptr);
    cudaGetSymbolAddress((void**)&cursor, g_cursor);
    cudaGetSymbolAddress((void**)&csrc, g_csrc);
    cudaGetSymbolAddress((void**)&bsum, g_bsum);
    cudaGetSymbolAddress((void**)&stats, g_stats);
    cudaGetSymbolAddress((void**)&wth0, g_wthi);
    cudaGetSymbolAddress((void**)&wtl0, g_wtlo);
    cudaGetSymbolAddress((void**)&fwth, g_fwth);
    cudaGetSymbolAddress((void**)&fwtl, g_fwtl);
    wth1 = wth0 + H * H;
    wtl1 = wtl0 + H * H;
    cudaGetSymbolAddress((void**)&lscr, g_logits_scratch);

    float* lsm = (float*)d_out;
    float* logits = (out_size >= 2 * n * CC) ? (lsm + (size_t)n * CC) : lscr;

    static cudaStream_t saux = nullptr;
    static cudaEvent_t ev0 = nullptr, evdis = nullptr, evg1 = nullptr,
                       evw2 = nullptr, evw3 = nullptr, evwh = nullptr;
    if (!saux) {
        cudaStreamCreateWithFlags(&saux, cudaStreamNonBlocking);
        cudaEventCreateWithFlags(&ev0, cudaEventDisableTiming);
        cudaEventCreateWithFlags(&evdis, cudaEventDisableTiming);
        cudaEventCreateWithFlags(&evg1, cudaEventDisableTiming);
        cudaEventCreateWithFlags(&evw2, cudaEventDisableTiming);
        cudaEventCreateWithFlags(&evw3, cudaEventDisableTiming);
        cudaEventCreateWithFlags(&evwh, cudaEventDisableTiming);
    }
    cudaStream_t s0 = 0;

    int nb = (n + 255) / 256;
    int ebks = (e + 255) / 256;
    int gemm_blocks = (n + 127) / 128;
    int agg_blocks = (n + 7) / 8;
    int scan_blocks = (n + 1023) / 1024;
    int ws_blocks = (H * H + 255) / 256;
    int wsh_blocks = (H * CC + 255) / 256;
    int sh_blocks = (n * 32 + 255) / 256;

    float* st0 = stats;
    float* st1 = stats + 256;
    float* st2 = stats + 512;

    cudaEventRecord(ev0, s0);
    cudaStreamWaitEvent(saux, ev0, 0);

    // ---- s0: CSR build ----
    k_zero_cnt<<<nb, 256, 0, s0>>>(cnt, stats, n);
    k_count<<<ebks, 256, 0, s0>>>(dst, cnt, e);
    k_scan_blk<<<scan_blocks, 1024, 0, s0>>>(cnt, rowptr, bsum, dis, n);
    cudaEventRecord(evdis, s0);
    k_scan_add<<<scan_blocks, 1024, 0, s0>>>(rowptr, cursor, bsum, n, e);
    k_fill<<<ebks, 256, 0, s0>>>(src, dst, cursor, csrc, e);

    // ---- saux: wsplit1 -> gemm1 (no dis wait, unscaled) -> scale after dis -> wsplits ----
    k_wsplit<<<ws_blocks, 256, 0, saux>>>(W1, wth0, wtl0);
    k_gemm_mma<<<gemm_blocks, 256, 0, saux>>>(x, (const unsigned*)wth0, (const unsigned*)wtl0,
                                              nullptr, nullptr, nullptr, nullptr, hw, n);
    cudaStreamWaitEvent(saux, evdis, 0);
    k_scale_hw<<<sh_blocks, 256, 0, saux>>>(hw, dis, n);
    cudaEventRecord(evg1, saux);
    k_wsplit<<<ws_blocks, 256, 0, saux>>>(W2, wth1, wtl1);
    cudaEventRecord(evw2, saux);
    k_wsplit<<<ws_blocks, 256, 0, saux>>>(W3, wth0, wtl0);
    cudaEventRecord(evw3, saux);
    k_wsplit_head<<<wsh_blocks, 256, 0, saux>>>(fcW, fwth, fwtl);
    cudaEventRecord(evwh, saux);

    // ---- s0: layer 1 aggregate ----
    cudaStreamWaitEvent(s0, evg1, 0);
    k_aggregate<<<agg_blocks, 256, 0, s0>>>(hw, rowptr, csrc, b1, dis, agg, st0, n);

    // ---- layer 2 ----
    cudaStreamWaitEvent(s0, evw2, 0);
    k_gemm_mma<<<gemm_blocks, 256, 0, s0>>>(agg, (const unsigned*)wth1, (const unsigned*)wtl1,
                                            g1, be1, st0, dis, hw, n);
    k_aggregate<<<agg_blocks, 256, 0, s0>>>(hw, rowptr, csrc, b2, dis, agg, st1, n);

    // ---- layer 3 ----
    cudaStreamWaitEvent(s0, evw3, 0);
    k_gemm_mma<<<gemm_blocks, 256, 0, s0>>>(agg, (const unsigned*)wth0, (const unsigned*)wtl0,
                                            g2, be2, st1, dis, hw, n);
    k_aggregate<<<agg_blocks, 256, 0, s0>>>(hw, rowptr, csrc, b3, dis, agg, st2, n);

    // ---- head (MMA) ----
    cudaStreamWaitEvent(s0, evwh, 0);
    k_head_mma<<<gemm_blocks, 256, 0, s0>>>(agg, (const unsigned*)fwth, (const unsigned*)fwtl,
                                            fcb, g3, be3, st2, lsm, logits, n);
}